// round 15
// baseline (speedup 1.0000x reference)
#include <cuda_runtime.h>
#include <cuda_bf16.h>
#include <math.h>
#include <stdint.h>

#define BB 512
#define SS 256
#define ID 12
#define HH 256
#define AA 9
#define G4 1024   // 4*HH
#define NCTA 128

// -------- scratch (static device allocations; no runtime alloc) --------
static __device__ float g_seq[(size_t)BB * SS * HH];   // emb, then reused as y0
static __device__ float g_xg[(size_t)BB * SS * G4];    // input gates, cols gc = j*4+gate
// hidden state as bf16 hi/lo, ping-pong: [ping][hi=0/lo=1][b*HH+j]
static __device__ __nv_bfloat16 g_hbf[2][2][BB * HH];
// per-batch-group barriers: 16 groups of 8 CTAs; 128B stride kills line contention
static __device__ unsigned g_cnt2[16 * 32];
static __device__ volatile unsigned g_gen2[16 * 32];

__device__ __forceinline__ float sigm(float x) { return 1.f / (1.f + expf(-x)); }

__device__ __forceinline__ uint32_t smem_u32(const void* p) {
    uint32_t a;
    asm("{ .reg .u64 t; cvta.to.shared.u64 t, %1; cvt.u32.u64 %0, t; }" : "=r"(a) : "l"(p));
    return a;
}

// 8-CTA batch-group barrier
__device__ __forceinline__ void group_sync(int grp) {
    __threadfence();
    __syncthreads();
    if (threadIdx.x == 0) {
        int gi = grp * 32;
        unsigned old = g_gen2[gi];
        if (atomicAdd(&g_cnt2[gi], 1u) == 7u) {
            g_cnt2[gi] = 0;
            __threadfence();
            g_gen2[gi] = old + 1;
        } else {
            while (g_gen2[gi] == old) __nanosleep(10);
            __threadfence();
        }
    }
    __syncthreads();
}

// ---------------- warp-MMA helpers ----------------
__device__ __forceinline__ void ldm4(uint32_t* r, uint32_t addr) {
    asm volatile("ldmatrix.sync.aligned.m8n8.x4.shared.b16 {%0,%1,%2,%3}, [%4];"
                 : "=r"(r[0]), "=r"(r[1]), "=r"(r[2]), "=r"(r[3]) : "r"(addr));
}

__device__ __forceinline__ void mma_bf16(float* d, const uint32_t* a, uint32_t b0, uint32_t b1) {
    asm volatile(
        "mma.sync.aligned.m16n8k16.row.col.f32.bf16.bf16.f32 "
        "{%0,%1,%2,%3}, {%4,%5,%6,%7}, {%8,%9}, {%0,%1,%2,%3};"
        : "+f"(d[0]), "+f"(d[1]), "+f"(d[2]), "+f"(d[3])
        : "r"(a[0]), "r"(a[1]), "r"(a[2]), "r"(a[3]), "r"(b0), "r"(b1));
}

__device__ __forceinline__ uint32_t pk2(float a, float b) {
    return (uint32_t)__bfloat16_as_ushort(__float2bfloat16(a)) |
           ((uint32_t)__bfloat16_as_ushort(__float2bfloat16(b)) << 16);
}

// fp32x4 -> bf16 hi (8B) + bf16 lo residual (8B)
__device__ __forceinline__ void split_store(char* hp, char* lp, float4 v) {
    float hx = __bfloat162float(__float2bfloat16(v.x));
    float hy = __bfloat162float(__float2bfloat16(v.y));
    float hz = __bfloat162float(__float2bfloat16(v.z));
    float hw = __bfloat162float(__float2bfloat16(v.w));
    uint64_t hi = (uint64_t)pk2(v.x, v.y) | ((uint64_t)pk2(v.z, v.w) << 32);
    uint64_t lo = (uint64_t)pk2(v.x - hx, v.y - hy) | ((uint64_t)pk2(v.z - hz, v.w - hw) << 32);
    *(uint64_t*)hp = hi;
    *(uint64_t*)lp = lo;
}

// -------- emb = relu(x @ W_emb^T + b_emb) --------
__global__ void emb_kernel(const float* __restrict__ x,
                           const float* __restrict__ W,
                           const float* __restrict__ bias) {
    __shared__ float ws[HH * ID];
    __shared__ float xs[8][ID];
    int tid = threadIdx.x;
    for (int i = tid; i < HH * ID; i += 256) ws[i] = W[i];
    size_t row0 = (size_t)blockIdx.x * 8;
    if (tid < 8 * ID) xs[tid / ID][tid % ID] = x[row0 * ID + tid];
    __syncthreads();
    float b = bias[tid];
#pragma unroll
    for (int r = 0; r < 8; r++) {
        float acc = b;
#pragma unroll
        for (int i = 0; i < ID; i++) acc = fmaf(xs[r][i], ws[tid * ID + i], acc);
        g_seq[(row0 + r) * HH + tid] = fmaxf(acc, 0.f);
    }
}

// ===================== tensor-core xg GEMM: 512 threads, warp tile 32x32 ============
#define RS 136
#define OFF_AHI 0
#define OFF_ALO (128 * RS * 2)               // 34816
#define OFF_BHI (2 * 128 * RS * 2)           // 69632
#define OFF_BLO (3 * 128 * RS * 2)           // 104448
#define OFF_BIAS (4 * 128 * RS * 2)          // 139264
#define XG_SMEM (OFF_BIAS + 512)             // 139776

__global__ void __launch_bounds__(512, 1) xg_mma(const float* __restrict__ wih,
                                                 const float* __restrict__ bih,
                                                 const float* __restrict__ bhh) {
    extern __shared__ char sp[];
    const uint32_t sb = smem_u32(sp);
    float* bias_s = (float*)(sp + OFF_BIAS);

    const int tid = threadIdx.x;
    const int lane = tid & 31;
    const int w = tid >> 5;
    const int wm0 = (w & 3) * 32;
    const int wn0 = (w >> 2) * 32;
    const int n0 = blockIdx.x * 128;
    const int m0 = blockIdx.y * 128;

    if (tid < 128) {
        int gc = n0 + tid;
        int wr = ((gc & 3) << 8) | (gc >> 2);
        bias_s[tid] = bih[wr] + bhh[wr];
    }

    float acc[2][4][4];
#pragma unroll
    for (int i = 0; i < 2; i++)
#pragma unroll
        for (int j = 0; j < 4; j++)
#pragma unroll
            for (int q = 0; q < 4; q++) acc[i][j][q] = 0.f;

    const int a_row = (lane & 15);
    const int a_kof = (lane >> 4) << 3;
    const int b_row = (lane & 7) + ((lane >> 4) << 3);
    const int b_kof = ((lane >> 3) & 1) << 3;

#pragma unroll
    for (int ch = 0; ch < 2; ch++) {
        const int kc0 = ch << 7;
#pragma unroll
        for (int q = 0; q < 8; q++) {
            int p = tid + (q << 9);
            int r = p >> 5;
            int k = (p & 31) << 2;
            uint32_t so = (uint32_t)(r * RS + k) * 2;
            float4 va = *(const float4*)&g_seq[(size_t)(m0 + r) * HH + kc0 + k];
            split_store(sp + OFF_AHI + so, sp + OFF_ALO + so, va);
            int gc = n0 + r;
            int wr = ((gc & 3) << 8) | (gc >> 2);
            float4 vb = *(const float4*)&wih[(size_t)wr * HH + kc0 + k];
            split_store(sp + OFF_BHI + so, sp + OFF_BLO + so, vb);
        }
        __syncthreads();

#pragma unroll
        for (int ks = 0; ks < 8; ks++) {
            const int kb = ks << 4;
            uint32_t ah[2][4], al[2][4];
#pragma unroll
            for (int mt = 0; mt < 2; mt++) {
                uint32_t off = (uint32_t)((wm0 + mt * 16 + a_row) * RS + kb + a_kof) * 2;
                ldm4(ah[mt], sb + OFF_AHI + off);
                ldm4(al[mt], sb + OFF_ALO + off);
            }
#pragma unroll
            for (int np = 0; np < 2; np++) {
                uint32_t off = (uint32_t)((wn0 + np * 16 + b_row) * RS + kb + b_kof) * 2;
                uint32_t bh[4], bl[4];
                ldm4(bh, sb + OFF_BHI + off);
                ldm4(bl, sb + OFF_BLO + off);
#pragma unroll
                for (int mt = 0; mt < 2; mt++) {
                    mma_bf16(acc[mt][np * 2], ah[mt], bh[0], bh[1]);
                    mma_bf16(acc[mt][np * 2], ah[mt], bl[0], bl[1]);
                    mma_bf16(acc[mt][np * 2], al[mt], bh[0], bh[1]);
                    mma_bf16(acc[mt][np * 2 + 1], ah[mt], bh[2], bh[3]);
                    mma_bf16(acc[mt][np * 2 + 1], ah[mt], bl[2], bl[3]);
                    mma_bf16(acc[mt][np * 2 + 1], al[mt], bh[2], bh[3]);
                }
            }
        }
        __syncthreads();
    }

    float* stg = (float*)sp;
    const int g = lane >> 2, tg = lane & 3;
#pragma unroll
    for (int mt = 0; mt < 2; mt++)
#pragma unroll
        for (int nt = 0; nt < 4; nt++) {
            int row = wm0 + mt * 16 + g;
            int col = wn0 + nt * 8 + tg * 2;
            *(float2*)&stg[row * 132 + col] = make_float2(acc[mt][nt][0], acc[mt][nt][1]);
            *(float2*)&stg[(row + 8) * 132 + col] = make_float2(acc[mt][nt][2], acc[mt][nt][3]);
        }
    __syncthreads();

#pragma unroll
    for (int q = 0; q < 8; q++) {
        int p = tid + (q << 9);
        int r = p >> 5;
        int c = (p & 31) << 2;
        float4 o = *(const float4*)&stg[r * 132 + c];
        o.x += bias_s[c + 0];
        o.y += bias_s[c + 1];
        o.z += bias_s[c + 2];
        o.w += bias_s[c + 3];
        *(float4*)&g_xg[(size_t)(m0 + r) * G4 + n0 + c] = o;
    }
}

// ============ persistent LSTM layer: tensor-core recurrence (R13 base + bf16 h) =====
#define LRS 264
#define L_WHI 0
#define L_WLO (128 * LRS * 2)                // 67584
#define L_HHI (2 * 128 * LRS * 2)            // 135168
#define L_HLO (L_HHI + 32 * LRS * 2)         // 152064
#define L_STG (L_HLO + 32 * LRS * 2)         // 168960
#define LSTM_SMEM (L_STG + 32 * 132 * 4)     // 185856

template <bool WRITE_Y>
__global__ void __launch_bounds__(256, 1) lstm_layer(const float* __restrict__ whh,
                                                     float* __restrict__ out_h,
                                                     float* __restrict__ out_c) {
    extern __shared__ char sp[];
    const uint32_t sb = smem_u32(sp);
    float* stg = (float*)(sp + L_STG);

    const int tid = threadIdx.x;
    const int lane = tid & 31;
    const int w = tid >> 5;
    const int jb0 = (blockIdx.x & 7) << 5;
    const int grp = blockIdx.x >> 3;
    const int bb0 = grp << 5;

    // ---- stage weights bf16 hi/lo once ----
    {
        int c = tid & 127;
        int kh = (tid >> 7) << 7;
        int gate = c & 3, unit = c >> 2;
        const float* wrow = whh + (size_t)(gate * HH + jb0 + unit) * HH + kh;
#pragma unroll
        for (int q = 0; q < 32; q++) {
            float4 v = *(const float4*)(wrow + q * 4);
            uint32_t so = (uint32_t)(c * LRS + kh + q * 4) * 2;
            split_store(sp + L_WHI + so, sp + L_WLO + so, v);
        }
    }
    __syncthreads();

    const int a_row = lane & 15;
    const int a_kof = (lane >> 4) << 3;
    const int b_row = (lane & 7) + ((lane >> 4) << 3);
    const int b_kof = ((lane >> 3) & 1) << 3;
    const int wn0 = w << 4;              // this warp's 16 gate cols

    const int a4 = (tid >> 5) << 2;      // cell-update batch base
    const int jx = tid & 31;             // cell-update unit
    const int j = jb0 + jx;
    const int cb = tid >> 3;             // h-load batch row 0..31
    const int ck0 = (tid & 7) << 5;      // h-load col base (32 bf16 per thread)

    float c_reg[4] = {0.f, 0.f, 0.f, 0.f};
    float hl[4] = {0.f, 0.f, 0.f, 0.f};

    for (int t = 0; t < SS; t++) {
        // prefetch this step's xg
        float4 xgv[4];
#pragma unroll
        for (int r = 0; r < 4; r++)
            xgv[r] = *(const float4*)&g_xg[((size_t)(bb0 + a4 + r) * SS + t) * G4 + (size_t)j * 4];

        if (t > 0) {
            // ---- copy h_prev bf16 hi/lo straight into ldmatrix tiles (pure copies) ----
            const __nv_bfloat16* phi = g_hbf[t & 1][0] + (size_t)(bb0 + cb) * HH + ck0;
            const __nv_bfloat16* plo = g_hbf[t & 1][1] + (size_t)(bb0 + cb) * HH + ck0;
            uint32_t sho = (uint32_t)(cb * LRS + ck0) * 2;
#pragma unroll
            for (int q = 0; q < 4; q++) {
                uint4 vh = __ldcg((const uint4*)(phi + q * 8));
                uint4 vl = __ldcg((const uint4*)(plo + q * 8));
                *(uint4*)(sp + L_HHI + sho + q * 16) = vh;
                *(uint4*)(sp + L_HLO + sho + q * 16) = vl;
            }
            __syncthreads();

            // ---- warp MMA: D[32 x 16cols] over K=256, 3-term bf16 split ----
            float acc[2][2][4];
#pragma unroll
            for (int mt = 0; mt < 2; mt++)
#pragma unroll
                for (int nt = 0; nt < 2; nt++)
#pragma unroll
                    for (int q = 0; q < 4; q++) acc[mt][nt][q] = 0.f;

#pragma unroll
            for (int ks = 0; ks < 16; ks++) {
                const int kb = ks << 4;
                uint32_t ah[2][4], al[2][4], bh[4], bl[4];
#pragma unroll
                for (int mt = 0; mt < 2; mt++) {
                    uint32_t off = (uint32_t)((mt * 16 + a_row) * LRS + kb + a_kof) * 2;
                    ldm4(ah[mt], sb + L_HHI + off);
                    ldm4(al[mt], sb + L_HLO + off);
                }
                {
                    uint32_t off = (uint32_t)((wn0 + b_row) * LRS + kb + b_kof) * 2;
                    ldm4(bh, sb + L_WHI + off);
                    ldm4(bl, sb + L_WLO + off);
                }
#pragma unroll
                for (int mt = 0; mt < 2; mt++) {
                    mma_bf16(acc[mt][0], ah[mt], bh[0], bh[1]);
                    mma_bf16(acc[mt][0], ah[mt], bl[0], bl[1]);
                    mma_bf16(acc[mt][0], al[mt], bh[0], bh[1]);
                    mma_bf16(acc[mt][1], ah[mt], bh[2], bh[3]);
                    mma_bf16(acc[mt][1], ah[mt], bl[2], bl[3]);
                    mma_bf16(acc[mt][1], al[mt], bh[2], bh[3]);
                }
            }

            // ---- stage acc -> stg[32][132] ----
            int gg = lane >> 2, tg = lane & 3;
#pragma unroll
            for (int mt = 0; mt < 2; mt++)
#pragma unroll
                for (int nt = 0; nt < 2; nt++) {
                    int row = mt * 16 + gg;
                    int col = wn0 + nt * 8 + tg * 2;
                    *(float2*)&stg[row * 132 + col] = make_float2(acc[mt][nt][0], acc[mt][nt][1]);
                    *(float2*)&stg[(row + 8) * 132 + col] = make_float2(acc[mt][nt][2], acc[mt][nt][3]);
                }
            __syncthreads();
        }

        // ---- cell update; h written as bf16 hi/lo (identical values to old split) ----
        __nv_bfloat16* ghi = g_hbf[(t & 1) ^ 1][0];
        __nv_bfloat16* glo = g_hbf[(t & 1) ^ 1][1];
#pragma unroll
        for (int r = 0; r < 4; r++) {
            int bl_ = a4 + r;
            float4 gv = (t > 0) ? *(const float4*)&stg[bl_ * 132 + (jx << 2)]
                                : make_float4(0.f, 0.f, 0.f, 0.f);
            float iv = sigm(gv.x + xgv[r].x);
            float fv = sigm(gv.y + xgv[r].y);
            float gt = tanhf(gv.z + xgv[r].z);
            float ov = sigm(gv.w + xgv[r].w);
            c_reg[r] = fmaf(fv, c_reg[r], iv * gt);
            float hn = ov * tanhf(c_reg[r]);
            hl[r] = hn;
            int b = bb0 + bl_;
            __nv_bfloat16 hhi = __float2bfloat16(hn);
            ghi[(size_t)b * HH + j] = hhi;
            glo[(size_t)b * HH + j] = __float2bfloat16(hn - __bfloat162float(hhi));
            if (WRITE_Y) g_seq[((size_t)b * SS + t) * HH + j] = hn;
        }

        group_sync(grp);
    }

    // epilogue: final h/c from registers (head reads out_h directly)
#pragma unroll
    for (int r = 0; r < 4; r++) {
        size_t idx = (size_t)(bb0 + a4 + r) * HH + j;
        out_h[idx] = hl[r];
        out_c[idx] = c_reg[r];
    }
}

// -------- head: layernorm(h1) -> relu(w1) -> w2 -> mask --------
__global__ void head_kernel(const float* __restrict__ h1,
                            const float* __restrict__ mask,
                            const float* __restrict__ ln_g, const float* __restrict__ ln_b,
                            const float* __restrict__ w1, const float* __restrict__ b1,
                            const float* __restrict__ w2, const float* __restrict__ b2,
                            float* __restrict__ out_logits) {
    int b = blockIdx.x;
    int tid = threadIdx.x;
    __shared__ float sh[HH];
    __shared__ float r1[8], r2[8];
    __shared__ float stats[2];
    __shared__ float hdn[32];

    float v = h1[(size_t)b * HH + tid];
    float s1 = v, s2 = v * v;
#pragma unroll
    for (int off = 16; off > 0; off >>= 1) {
        s1 += __shfl_down_sync(0xffffffffu, s1, off);
        s2 += __shfl_down_sync(0xffffffffu, s2, off);
    }
    if ((tid & 31) == 0) { r1[tid >> 5] = s1; r2[tid >> 5] = s2; }
    __syncthreads();
    if (tid == 0) {
        float t1 = 0.f, t2 = 0.f;
        for (int i = 0; i < 8; i++) { t1 += r1[i]; t2 += r2[i]; }
        float mu = t1 * (1.f / HH);
        float var = t2 * (1.f / HH) - mu * mu;
        stats[0] = mu;
        stats[1] = rsqrtf(var + 1e-5f);
    }
    __syncthreads();
    sh[tid] = (v - stats[0]) * stats[1] * ln_g[tid] + ln_b[tid];
    __syncthreads();

    int u = tid >> 3, p = tid & 7;
    float part = 0.f;
#pragma unroll
    for (int k = p; k < HH; k += 8) part = fmaf(sh[k], w1[u * HH + k], part);
    part += __shfl_down_sync(0xffffffffu, part, 4);
    part += __shfl_down_sync(0xffffffffu, part, 2);
    part += __shfl_down_sync(0xffffffffu, part, 1);
    if (p == 0) hdn[u] = fmaxf(part + b1[u], 0.f);
    __syncthreads();

    if (tid < AA) {
        float acc = b2[tid];
#pragma unroll
        for (int k = 0; k < 32; k++) acc = fmaf(hdn[k], w2[tid * 32 + k], acc);
        acc += (1.f - mask[(size_t)b * AA + tid]) * -1e9f;
        out_logits[(size_t)b * AA + tid] = acc;
    }
}

extern "C" void kernel_launch(void* const* d_in, const int* in_sizes, int n_in,
                              void* d_out, int out_size) {
    (void)in_sizes; (void)n_in; (void)out_size;
    const float* x     = (const float*)d_in[0];
    const float* mask  = (const float*)d_in[1];
    const float* W_emb = (const float*)d_in[2];
    const float* b_emb = (const float*)d_in[3];
    const float* w_ih0 = (const float*)d_in[4];
    const float* w_hh0 = (const float*)d_in[5];
    const float* b_ih0 = (const float*)d_in[6];
    const float* b_hh0 = (const float*)d_in[7];
    const float* w_ih1 = (const float*)d_in[8];
    const float* w_hh1 = (const float*)d_in[9];
    const float* b_ih1 = (const float*)d_in[10];
    const float* b_hh1 = (const float*)d_in[11];
    const float* ln_g  = (const float*)d_in[12];
    const float* ln_b  = (const float*)d_in[13];
    const float* w1    = (const float*)d_in[14];
    const float* b1    = (const float*)d_in[15];
    const float* w2    = (const float*)d_in[16];
    const float* b2    = (const float*)d_in[17];

    float* out        = (float*)d_out;
    float* out_logits = out;
    float* out_h0     = out + BB * AA;
    float* out_h1     = out_h0 + BB * HH;
    float* out_c0     = out_h1 + BB * HH;
    float* out_c1     = out_c0 + BB * HH;

    cudaFuncSetAttribute(lstm_layer<true>,
                         cudaFuncAttributeMaxDynamicSharedMemorySize, LSTM_SMEM);
    cudaFuncSetAttribute(lstm_layer<false>,
                         cudaFuncAttributeMaxDynamicSharedMemorySize, LSTM_SMEM);
    cudaFuncSetAttribute(xg_mma,
                         cudaFuncAttributeMaxDynamicSharedMemorySize, XG_SMEM);

    dim3 xg_grid(G4 / 128, (BB * SS) / 128);   // (8, 1024)

    emb_kernel<<<(BB * SS) / 8, 256>>>(x, W_emb, b_emb);

    // layer 0
    xg_mma<<<xg_grid, 512, XG_SMEM>>>(w_ih0, b_ih0, b_hh0);
    lstm_layer<true><<<NCTA, 256, LSTM_SMEM>>>(w_hh0, out_h0, out_c0);

    // layer 1 (y0 in g_seq)
    xg_mma<<<xg_grid, 512, XG_SMEM>>>(w_ih1, b_ih1, b_hh1);
    lstm_layer<false><<<NCTA, 256, LSTM_SMEM>>>(w_hh1, out_h1, out_c1);

    // head: last == final h1 (written to out_h1 by lstm epilogue)
    head_kernel<<<BB, 256>>>(out_h1, mask, ln_g, ln_b, w1, b1, w2, b2, out_logits);
}

// round 16
// speedup vs baseline: 1.0363x; 1.0363x over previous
#include <cuda_runtime.h>
#include <cuda_bf16.h>
#include <math.h>
#include <stdint.h>

#define BB 512
#define SS 256
#define ID 12
#define HH 256
#define AA 9
#define G4 1024   // 4*HH
#define NCTA 128

// -------- scratch (static device allocations; no runtime alloc) --------
static __device__ float g_seq[(size_t)BB * SS * HH];   // emb, then reused as y0
static __device__ float g_xg[(size_t)BB * SS * G4];    // input gates, cols gc = j*4+gate
static __device__ float g_hbuf[2][BB * HH];            // ping-pong hidden state (fp32)
// per-batch-group barriers: 16 groups of 8 CTAs; 128B stride kills line contention
static __device__ unsigned g_cnt2[16 * 32];
static __device__ volatile unsigned g_gen2[16 * 32];

__device__ __forceinline__ float sigm(float x) { return 1.f / (1.f + expf(-x)); }

__device__ __forceinline__ uint32_t smem_u32(const void* p) {
    uint32_t a;
    asm("{ .reg .u64 t; cvta.to.shared.u64 t, %1; cvt.u32.u64 %0, t; }" : "=r"(a) : "l"(p));
    return a;
}

// 8-CTA batch-group barrier
__device__ __forceinline__ void group_sync(int grp) {
    __threadfence();
    __syncthreads();
    if (threadIdx.x == 0) {
        int gi = grp * 32;
        unsigned old = g_gen2[gi];
        if (atomicAdd(&g_cnt2[gi], 1u) == 7u) {
            g_cnt2[gi] = 0;
            __threadfence();
            g_gen2[gi] = old + 1;
        } else {
            while (g_gen2[gi] == old) __nanosleep(10);
            __threadfence();
        }
    }
    __syncthreads();
}

// ---------------- warp-MMA helpers ----------------
__device__ __forceinline__ void ldm4(uint32_t* r, uint32_t addr) {
    asm volatile("ldmatrix.sync.aligned.m8n8.x4.shared.b16 {%0,%1,%2,%3}, [%4];"
                 : "=r"(r[0]), "=r"(r[1]), "=r"(r[2]), "=r"(r[3]) : "r"(addr));
}

__device__ __forceinline__ void mma_bf16(float* d, const uint32_t* a, uint32_t b0, uint32_t b1) {
    asm volatile(
        "mma.sync.aligned.m16n8k16.row.col.f32.bf16.bf16.f32 "
        "{%0,%1,%2,%3}, {%4,%5,%6,%7}, {%8,%9}, {%0,%1,%2,%3};"
        : "+f"(d[0]), "+f"(d[1]), "+f"(d[2]), "+f"(d[3])
        : "r"(a[0]), "r"(a[1]), "r"(a[2]), "r"(a[3]), "r"(b0), "r"(b1));
}

__device__ __forceinline__ uint32_t pk2(float a, float b) {
    return (uint32_t)__bfloat16_as_ushort(__float2bfloat16(a)) |
           ((uint32_t)__bfloat16_as_ushort(__float2bfloat16(b)) << 16);
}

// fp32x4 -> bf16 hi (8B) + bf16 lo residual (8B)
__device__ __forceinline__ void split_store(char* hp, char* lp, float4 v) {
    float hx = __bfloat162float(__float2bfloat16(v.x));
    float hy = __bfloat162float(__float2bfloat16(v.y));
    float hz = __bfloat162float(__float2bfloat16(v.z));
    float hw = __bfloat162float(__float2bfloat16(v.w));
    uint64_t hi = (uint64_t)pk2(v.x, v.y) | ((uint64_t)pk2(v.z, v.w) << 32);
    uint64_t lo = (uint64_t)pk2(v.x - hx, v.y - hy) | ((uint64_t)pk2(v.z - hz, v.w - hw) << 32);
    *(uint64_t*)hp = hi;
    *(uint64_t*)lp = lo;
}

// -------- emb = relu(x @ W_emb^T + b_emb) --------
__global__ void emb_kernel(const float* __restrict__ x,
                           const float* __restrict__ W,
                           const float* __restrict__ bias) {
    __shared__ float ws[HH * ID];
    __shared__ float xs[8][ID];
    int tid = threadIdx.x;
    for (int i = tid; i < HH * ID; i += 256) ws[i] = W[i];
    size_t row0 = (size_t)blockIdx.x * 8;
    if (tid < 8 * ID) xs[tid / ID][tid % ID] = x[row0 * ID + tid];
    __syncthreads();
    float b = bias[tid];
#pragma unroll
    for (int r = 0; r < 8; r++) {
        float acc = b;
#pragma unroll
        for (int i = 0; i < ID; i++) acc = fmaf(xs[r][i], ws[tid * ID + i], acc);
        g_seq[(row0 + r) * HH + tid] = fmaxf(acc, 0.f);
    }
}

// ===================== tensor-core xg GEMM: 512 threads, warp tile 32x32 ============
#define RS 136
#define OFF_AHI 0
#define OFF_ALO (128 * RS * 2)               // 34816
#define OFF_BHI (2 * 128 * RS * 2)           // 69632
#define OFF_BLO (3 * 128 * RS * 2)           // 104448
#define OFF_BIAS (4 * 128 * RS * 2)          // 139264
#define XG_SMEM (OFF_BIAS + 512)             // 139776

__global__ void __launch_bounds__(512, 1) xg_mma(const float* __restrict__ wih,
                                                 const float* __restrict__ bih,
                                                 const float* __restrict__ bhh) {
    extern __shared__ char sp[];
    const uint32_t sb = smem_u32(sp);
    float* bias_s = (float*)(sp + OFF_BIAS);

    const int tid = threadIdx.x;
    const int lane = tid & 31;
    const int w = tid >> 5;
    const int wm0 = (w & 3) * 32;
    const int wn0 = (w >> 2) * 32;
    const int n0 = blockIdx.x * 128;
    const int m0 = blockIdx.y * 128;

    if (tid < 128) {
        int gc = n0 + tid;
        int wr = ((gc & 3) << 8) | (gc >> 2);
        bias_s[tid] = bih[wr] + bhh[wr];
    }

    float acc[2][4][4];
#pragma unroll
    for (int i = 0; i < 2; i++)
#pragma unroll
        for (int j = 0; j < 4; j++)
#pragma unroll
            for (int q = 0; q < 4; q++) acc[i][j][q] = 0.f;

    const int a_row = (lane & 15);
    const int a_kof = (lane >> 4) << 3;
    const int b_row = (lane & 7) + ((lane >> 4) << 3);
    const int b_kof = ((lane >> 3) & 1) << 3;

#pragma unroll
    for (int ch = 0; ch < 2; ch++) {
        const int kc0 = ch << 7;
#pragma unroll
        for (int q = 0; q < 8; q++) {
            int p = tid + (q << 9);
            int r = p >> 5;
            int k = (p & 31) << 2;
            uint32_t so = (uint32_t)(r * RS + k) * 2;
            float4 va = *(const float4*)&g_seq[(size_t)(m0 + r) * HH + kc0 + k];
            split_store(sp + OFF_AHI + so, sp + OFF_ALO + so, va);
            int gc = n0 + r;
            int wr = ((gc & 3) << 8) | (gc >> 2);
            float4 vb = *(const float4*)&wih[(size_t)wr * HH + kc0 + k];
            split_store(sp + OFF_BHI + so, sp + OFF_BLO + so, vb);
        }
        __syncthreads();

#pragma unroll
        for (int ks = 0; ks < 8; ks++) {
            const int kb = ks << 4;
            uint32_t ah[2][4], al[2][4];
#pragma unroll
            for (int mt = 0; mt < 2; mt++) {
                uint32_t off = (uint32_t)((wm0 + mt * 16 + a_row) * RS + kb + a_kof) * 2;
                ldm4(ah[mt], sb + OFF_AHI + off);
                ldm4(al[mt], sb + OFF_ALO + off);
            }
#pragma unroll
            for (int np = 0; np < 2; np++) {
                uint32_t off = (uint32_t)((wn0 + np * 16 + b_row) * RS + kb + b_kof) * 2;
                uint32_t bh[4], bl[4];
                ldm4(bh, sb + OFF_BHI + off);
                ldm4(bl, sb + OFF_BLO + off);
#pragma unroll
                for (int mt = 0; mt < 2; mt++) {
                    mma_bf16(acc[mt][np * 2], ah[mt], bh[0], bh[1]);
                    mma_bf16(acc[mt][np * 2], ah[mt], bl[0], bl[1]);
                    mma_bf16(acc[mt][np * 2], al[mt], bh[0], bh[1]);
                    mma_bf16(acc[mt][np * 2 + 1], ah[mt], bh[2], bh[3]);
                    mma_bf16(acc[mt][np * 2 + 1], ah[mt], bl[2], bl[3]);
                    mma_bf16(acc[mt][np * 2 + 1], al[mt], bh[2], bh[3]);
                }
            }
        }
        __syncthreads();
    }

    float* stg = (float*)sp;
    const int g = lane >> 2, tg = lane & 3;
#pragma unroll
    for (int mt = 0; mt < 2; mt++)
#pragma unroll
        for (int nt = 0; nt < 4; nt++) {
            int row = wm0 + mt * 16 + g;
            int col = wn0 + nt * 8 + tg * 2;
            *(float2*)&stg[row * 132 + col] = make_float2(acc[mt][nt][0], acc[mt][nt][1]);
            *(float2*)&stg[(row + 8) * 132 + col] = make_float2(acc[mt][nt][2], acc[mt][nt][3]);
        }
    __syncthreads();

#pragma unroll
    for (int q = 0; q < 8; q++) {
        int p = tid + (q << 9);
        int r = p >> 5;
        int c = (p & 31) << 2;
        float4 o = *(const float4*)&stg[r * 132 + c];
        o.x += bias_s[c + 0];
        o.y += bias_s[c + 1];
        o.z += bias_s[c + 2];
        o.w += bias_s[c + 3];
        *(float4*)&g_xg[(size_t)(m0 + r) * G4 + n0 + c] = o;
    }
}

// ============ persistent LSTM layer: R13 dataflow, 512 threads / 16 warps ===========
// warp tile M16 x N16 (was M32 x N16 at 8 warps): same total HMMA, half chain length,
// 4 warps/SMSP to keep the tensor pipe fed.
#define LRS 264
#define L_WHI 0
#define L_WLO (128 * LRS * 2)                // 67584
#define L_HHI (2 * 128 * LRS * 2)            // 135168
#define L_HLO (L_HHI + 32 * LRS * 2)         // 152064
#define L_STG (L_HLO + 32 * LRS * 2)         // 168960
#define LSTM_SMEM (L_STG + 32 * 132 * 4)     // 185856  (< 227KB cap)

template <bool WRITE_Y>
__global__ void __launch_bounds__(512, 1) lstm_layer(const float* __restrict__ whh,
                                                     float* __restrict__ out_h,
                                                     float* __restrict__ out_c) {
    extern __shared__ char sp[];
    const uint32_t sb = smem_u32(sp);
    float* stg = (float*)(sp + L_STG);

    const int tid = threadIdx.x;
    const int lane = tid & 31;
    const int w = tid >> 5;                  // 0..15
    const int jb0 = (blockIdx.x & 7) << 5;
    const int grp = blockIdx.x >> 3;
    const int bb0 = grp << 5;

    // ---- stage weights bf16 hi/lo once (512 threads: 16 float4 each) ----
    {
        int c = tid & 127;
        int kh = (tid >> 7) << 6;            // 4 k-chunks of 64
        int gate = c & 3, unit = c >> 2;
        const float* wrow = whh + (size_t)(gate * HH + jb0 + unit) * HH + kh;
#pragma unroll
        for (int q = 0; q < 16; q++) {
            float4 v = *(const float4*)(wrow + q * 4);
            uint32_t so = (uint32_t)(c * LRS + kh + q * 4) * 2;
            split_store(sp + L_WHI + so, sp + L_WLO + so, v);
        }
    }
    __syncthreads();

    const int a_row = lane & 15;
    const int a_kof = (lane >> 4) << 3;
    const int b_row = (lane & 7) + ((lane >> 4) << 3);
    const int b_kof = ((lane >> 3) & 1) << 3;
    const int wm0 = (w & 1) << 4;            // 0 or 16
    const int wn0 = (w >> 1) << 4;           // 0..112: this warp's 16 gate cols

    const int a2 = (tid >> 5) << 1;          // cell-update batch pair base (0..30)
    const int jx = tid & 31;                 // cell-update unit
    const int j = jb0 + jx;
    const int cb = tid >> 4;                 // h-stage batch row 0..31
    const int ck = (tid & 15) << 2;          // h-stage k base (stride 64 per q)

    float c_reg[2] = {0.f, 0.f};
    float hl[2] = {0.f, 0.f};

    for (int t = 0; t < SS; t++) {
        // prefetch this step's xg (2 rows per thread)
        float4 xgv[2];
#pragma unroll
        for (int r = 0; r < 2; r++)
            xgv[r] = *(const float4*)&g_xg[((size_t)(bb0 + a2 + r) * SS + t) * G4 + (size_t)j * 4];

        if (t > 0) {
            // ---- convert h_prev slice [32 x 256] fp32 -> bf16 hi/lo (4 float4/thread) ----
            const float* hp = g_hbuf[t & 1] + (size_t)(bb0 + cb) * HH;
#pragma unroll
            for (int q = 0; q < 4; q++) {
                int k = ck + q * 64;
                float4 v = __ldcg((const float4*)(hp + k));
                uint32_t so = (uint32_t)(cb * LRS + k) * 2;
                split_store(sp + L_HHI + so, sp + L_HLO + so, v);
            }
            __syncthreads();

            // ---- warp MMA: D[16 x 16] over K=256, 3-term bf16 split ----
            float acc[2][4];
#pragma unroll
            for (int nt = 0; nt < 2; nt++)
#pragma unroll
                for (int q = 0; q < 4; q++) acc[nt][q] = 0.f;

#pragma unroll
            for (int ks = 0; ks < 16; ks++) {
                const int kb = ks << 4;
                uint32_t ah[4], al[4], bh[4], bl[4];
                {
                    uint32_t off = (uint32_t)((wm0 + a_row) * LRS + kb + a_kof) * 2;
                    ldm4(ah, sb + L_HHI + off);
                    ldm4(al, sb + L_HLO + off);
                }
                {
                    uint32_t off = (uint32_t)((wn0 + b_row) * LRS + kb + b_kof) * 2;
                    ldm4(bh, sb + L_WHI + off);
                    ldm4(bl, sb + L_WLO + off);
                }
                mma_bf16(acc[0], ah, bh[0], bh[1]);
                mma_bf16(acc[0], ah, bl[0], bl[1]);
                mma_bf16(acc[0], al, bh[0], bh[1]);
                mma_bf16(acc[1], ah, bh[2], bh[3]);
                mma_bf16(acc[1], ah, bl[2], bl[3]);
                mma_bf16(acc[1], al, bh[2], bh[3]);
            }

            // ---- stage acc -> stg[32][132] ----
            int gg = lane >> 2, tg = lane & 3;
#pragma unroll
            for (int nt = 0; nt < 2; nt++) {
                int row = wm0 + gg;
                int col = wn0 + nt * 8 + tg * 2;
                *(float2*)&stg[row * 132 + col] = make_float2(acc[nt][0], acc[nt][1]);
                *(float2*)&stg[(row + 8) * 132 + col] = make_float2(acc[nt][2], acc[nt][3]);
            }
            __syncthreads();
        }

        // ---- cell update (2 batch rows per thread) ----
        float* hnext = g_hbuf[(t & 1) ^ 1];
#pragma unroll
        for (int r = 0; r < 2; r++) {
            int bl_ = a2 + r;
            float4 gv = (t > 0) ? *(const float4*)&stg[bl_ * 132 + (jx << 2)]
                                : make_float4(0.f, 0.f, 0.f, 0.f);
            float iv = sigm(gv.x + xgv[r].x);
            float fv = sigm(gv.y + xgv[r].y);
            float gt = tanhf(gv.z + xgv[r].z);
            float ov = sigm(gv.w + xgv[r].w);
            c_reg[r] = fmaf(fv, c_reg[r], iv * gt);
            float hn = ov * tanhf(c_reg[r]);
            hl[r] = hn;
            int b = bb0 + bl_;
            hnext[(size_t)b * HH + j] = hn;
            if (WRITE_Y) g_seq[((size_t)b * SS + t) * HH + j] = hn;
        }

        group_sync(grp);
    }

    // epilogue: final h/c from registers (head reads out_h directly)
#pragma unroll
    for (int r = 0; r < 2; r++) {
        size_t idx = (size_t)(bb0 + a2 + r) * HH + j;
        out_h[idx] = hl[r];
        out_c[idx] = c_reg[r];
    }
}

// -------- head: layernorm(h1) -> relu(w1) -> w2 -> mask --------
__global__ void head_kernel(const float* __restrict__ h1,
                            const float* __restrict__ mask,
                            const float* __restrict__ ln_g, const float* __restrict__ ln_b,
                            const float* __restrict__ w1, const float* __restrict__ b1,
                            const float* __restrict__ w2, const float* __restrict__ b2,
                            float* __restrict__ out_logits) {
    int b = blockIdx.x;
    int tid = threadIdx.x;
    __shared__ float sh[HH];
    __shared__ float r1[8], r2[8];
    __shared__ float stats[2];
    __shared__ float hdn[32];

    float v = h1[(size_t)b * HH + tid];
    float s1 = v, s2 = v * v;
#pragma unroll
    for (int off = 16; off > 0; off >>= 1) {
        s1 += __shfl_down_sync(0xffffffffu, s1, off);
        s2 += __shfl_down_sync(0xffffffffu, s2, off);
    }
    if ((tid & 31) == 0) { r1[tid >> 5] = s1; r2[tid >> 5] = s2; }
    __syncthreads();
    if (tid == 0) {
        float t1 = 0.f, t2 = 0.f;
        for (int i = 0; i < 8; i++) { t1 += r1[i]; t2 += r2[i]; }
        float mu = t1 * (1.f / HH);
        float var = t2 * (1.f / HH) - mu * mu;
        stats[0] = mu;
        stats[1] = rsqrtf(var + 1e-5f);
    }
    __syncthreads();
    sh[tid] = (v - stats[0]) * stats[1] * ln_g[tid] + ln_b[tid];
    __syncthreads();

    int u = tid >> 3, p = tid & 7;
    float part = 0.f;
#pragma unroll
    for (int k = p; k < HH; k += 8) part = fmaf(sh[k], w1[u * HH + k], part);
    part += __shfl_down_sync(0xffffffffu, part, 4);
    part += __shfl_down_sync(0xffffffffu, part, 2);
    part += __shfl_down_sync(0xffffffffu, part, 1);
    if (p == 0) hdn[u] = fmaxf(part + b1[u], 0.f);
    __syncthreads();

    if (tid < AA) {
        float acc = b2[tid];
#pragma unroll
        for (int k = 0; k < 32; k++) acc = fmaf(hdn[k], w2[tid * 32 + k], acc);
        acc += (1.f - mask[(size_t)b * AA + tid]) * -1e9f;
        out_logits[(size_t)b * AA + tid] = acc;
    }
}

extern "C" void kernel_launch(void* const* d_in, const int* in_sizes, int n_in,
                              void* d_out, int out_size) {
    (void)in_sizes; (void)n_in; (void)out_size;
    const float* x     = (const float*)d_in[0];
    const float* mask  = (const float*)d_in[1];
    const float* W_emb = (const float*)d_in[2];
    const float* b_emb = (const float*)d_in[3];
    const float* w_ih0 = (const float*)d_in[4];
    const float* w_hh0 = (const float*)d_in[5];
    const float* b_ih0 = (const float*)d_in[6];
    const float* b_hh0 = (const float*)d_in[7];
    const float* w_ih1 = (const float*)d_in[8];
    const float* w_hh1 = (const float*)d_in[9];
    const float* b_ih1 = (const float*)d_in[10];
    const float* b_hh1 = (const float*)d_in[11];
    const float* ln_g  = (const float*)d_in[12];
    const float* ln_b  = (const float*)d_in[13];
    const float* w1    = (const float*)d_in[14];
    const float* b1    = (const float*)d_in[15];
    const float* w2    = (const float*)d_in[16];
    const float* b2    = (const float*)d_in[17];

    float* out        = (float*)d_out;
    float* out_logits = out;
    float* out_h0     = out + BB * AA;
    float* out_h1     = out_h0 + BB * HH;
    float* out_c0     = out_h1 + BB * HH;
    float* out_c1     = out_c0 + BB * HH;

    cudaFuncSetAttribute(lstm_layer<true>,
                         cudaFuncAttributeMaxDynamicSharedMemorySize, LSTM_SMEM);
    cudaFuncSetAttribute(lstm_layer<false>,
                         cudaFuncAttributeMaxDynamicSharedMemorySize, LSTM_SMEM);
    cudaFuncSetAttribute(xg_mma,
                         cudaFuncAttributeMaxDynamicSharedMemorySize, XG_SMEM);

    dim3 xg_grid(G4 / 128, (BB * SS) / 128);   // (8, 1024)

    emb_kernel<<<(BB * SS) / 8, 256>>>(x, W_emb, b_emb);

    // layer 0
    xg_mma<<<xg_grid, 512, XG_SMEM>>>(w_ih0, b_ih0, b_hh0);
    lstm_layer<true><<<NCTA, 512, LSTM_SMEM>>>(w_hh0, out_h0, out_c0);

    // layer 1 (y0 in g_seq)
    xg_mma<<<xg_grid, 512, XG_SMEM>>>(w_ih1, b_ih1, b_hh1);
    lstm_layer<false><<<NCTA, 512, LSTM_SMEM>>>(w_hh1, out_h1, out_c1);

    // head: last == final h1 (written to out_h1 by lstm epilogue)
    head_kernel<<<BB, 256>>>(out_h1, mask, ln_g, ln_b, w1, b1, w2, b2, out_logits);
}

// round 17
// speedup vs baseline: 1.1166x; 1.0775x over previous
#include <cuda_runtime.h>
#include <cuda_bf16.h>
#include <math.h>
#include <stdint.h>

#define BB 512
#define SS 256
#define ID 12
#define HH 256
#define AA 9
#define G4 1024   // 4*HH
#define NCTA 128

// -------- scratch (static device allocations; no runtime alloc) --------
// packed split format: u32 = bf16_hi(v) | bf16_lo(v - f32(hi)) << 16
static __device__ uint32_t g_seqp[(size_t)BB * SS * HH];  // emb, then y0 (packed)
static __device__ float    g_xg[(size_t)BB * SS * G4];    // input gates, cols gc = j*4+gate
static __device__ uint32_t g_hp[2][BB * HH];              // ping-pong hidden state (packed)
static __device__ uint32_t g_wsp0[G4 * HH];               // pre-split w_ih0 (permuted cols)
static __device__ uint32_t g_wsp1[G4 * HH];               // pre-split w_ih1
// per-batch-group barriers: 16 groups of 8 CTAs; 128B stride kills line contention
static __device__ unsigned g_cnt2[16 * 32];
static __device__ volatile unsigned g_gen2[16 * 32];

__device__ __forceinline__ float sigm(float x) { return 1.f / (1.f + expf(-x)); }

__device__ __forceinline__ uint32_t smem_u32(const void* p) {
    uint32_t a;
    asm("{ .reg .u64 t; cvta.to.shared.u64 t, %1; cvt.u32.u64 %0, t; }" : "=r"(a) : "l"(p));
    return a;
}

// 8-CTA batch-group barrier
__device__ __forceinline__ void group_sync(int grp) {
    __threadfence();
    __syncthreads();
    if (threadIdx.x == 0) {
        int gi = grp * 32;
        unsigned old = g_gen2[gi];
        if (atomicAdd(&g_cnt2[gi], 1u) == 7u) {
            g_cnt2[gi] = 0;
            __threadfence();
            g_gen2[gi] = old + 1;
        } else {
            while (g_gen2[gi] == old) __nanosleep(10);
            __threadfence();
        }
    }
    __syncthreads();
}

// ---------------- warp-MMA helpers ----------------
__device__ __forceinline__ void ldm4(uint32_t* r, uint32_t addr) {
    asm volatile("ldmatrix.sync.aligned.m8n8.x4.shared.b16 {%0,%1,%2,%3}, [%4];"
                 : "=r"(r[0]), "=r"(r[1]), "=r"(r[2]), "=r"(r[3]) : "r"(addr));
}

__device__ __forceinline__ void mma_bf16(float* d, const uint32_t* a, uint32_t b0, uint32_t b1) {
    asm volatile(
        "mma.sync.aligned.m16n8k16.row.col.f32.bf16.bf16.f32 "
        "{%0,%1,%2,%3}, {%4,%5,%6,%7}, {%8,%9}, {%0,%1,%2,%3};"
        : "+f"(d[0]), "+f"(d[1]), "+f"(d[2]), "+f"(d[3])
        : "r"(a[0]), "r"(a[1]), "r"(a[2]), "r"(a[3]), "r"(b0), "r"(b1));
}

// ---- packed-split helpers ----
__device__ __forceinline__ uint32_t packsplit(float v) {
    __nv_bfloat16 h = __float2bfloat16(v);
    float hf = __bfloat162float(h);
    __nv_bfloat16 l = __float2bfloat16(v - hf);
    return (uint32_t)__bfloat16_as_ushort(h) | ((uint32_t)__bfloat16_as_ushort(l) << 16);
}
__device__ __forceinline__ uint64_t up_hi(uint4 p) {
    uint32_t a = __byte_perm(p.x, p.y, 0x5410);
    uint32_t b = __byte_perm(p.z, p.w, 0x5410);
    return (uint64_t)a | ((uint64_t)b << 32);
}
__device__ __forceinline__ uint64_t up_lo(uint4 p) {
    uint32_t a = __byte_perm(p.x, p.y, 0x7632);
    uint32_t b = __byte_perm(p.z, p.w, 0x7632);
    return (uint64_t)a | ((uint64_t)b << 32);
}

// fp32x4 -> bf16 hi (8B) + bf16 lo residual (8B)  (used for one-time weight staging)
__device__ __forceinline__ uint32_t pk2(float a, float b) {
    return (uint32_t)__bfloat16_as_ushort(__float2bfloat16(a)) |
           ((uint32_t)__bfloat16_as_ushort(__float2bfloat16(b)) << 16);
}
__device__ __forceinline__ void split_store(char* hp, char* lp, float4 v) {
    float hx = __bfloat162float(__float2bfloat16(v.x));
    float hy = __bfloat162float(__float2bfloat16(v.y));
    float hz = __bfloat162float(__float2bfloat16(v.z));
    float hw = __bfloat162float(__float2bfloat16(v.w));
    uint64_t hi = (uint64_t)pk2(v.x, v.y) | ((uint64_t)pk2(v.z, v.w) << 32);
    uint64_t lo = (uint64_t)pk2(v.x - hx, v.y - hy) | ((uint64_t)pk2(v.z - hz, v.w - hw) << 32);
    *(uint64_t*)hp = hi;
    *(uint64_t*)lp = lo;
}

// -------- pre-split w_ih into packed scratch (permuted cols: gc -> wr) --------
__global__ void wsplit_kernel(const float* __restrict__ wih, uint32_t* __restrict__ dst) {
    int gc = blockIdx.x;
    int k = threadIdx.x;
    int wr = ((gc & 3) << 8) | (gc >> 2);
    dst[(size_t)gc * HH + k] = packsplit(wih[(size_t)wr * HH + k]);
}

// -------- emb = relu(x @ W_emb^T + b_emb), output packed --------
__global__ void emb_kernel(const float* __restrict__ x,
                           const float* __restrict__ W,
                           const float* __restrict__ bias) {
    __shared__ float ws[HH * ID];
    __shared__ float xs[8][ID];
    int tid = threadIdx.x;
    for (int i = tid; i < HH * ID; i += 256) ws[i] = W[i];
    size_t row0 = (size_t)blockIdx.x * 8;
    if (tid < 8 * ID) xs[tid / ID][tid % ID] = x[row0 * ID + tid];
    __syncthreads();
    float b = bias[tid];
#pragma unroll
    for (int r = 0; r < 8; r++) {
        float acc = b;
#pragma unroll
        for (int i = 0; i < ID; i++) acc = fmaf(xs[r][i], ws[tid * ID + i], acc);
        g_seqp[(row0 + r) * HH + tid] = packsplit(fmaxf(acc, 0.f));
    }
}

// ===================== tensor-core xg GEMM: 512 threads, warp tile 32x32 ============
// A and B arrive PRE-SPLIT packed; load phase = uint4 load + 4 PRMT + 2 STS.64.
#define RS 136
#define OFF_AHI 0
#define OFF_ALO (128 * RS * 2)               // 34816
#define OFF_BHI (2 * 128 * RS * 2)           // 69632
#define OFF_BLO (3 * 128 * RS * 2)           // 104448
#define OFF_BIAS (4 * 128 * RS * 2)          // 139264
#define XG_SMEM (OFF_BIAS + 512)             // 139776

__global__ void __launch_bounds__(512, 1) xg_mma(const uint32_t* __restrict__ wsp,
                                                 const float* __restrict__ bih,
                                                 const float* __restrict__ bhh) {
    extern __shared__ char sp[];
    const uint32_t sb = smem_u32(sp);
    float* bias_s = (float*)(sp + OFF_BIAS);

    const int tid = threadIdx.x;
    const int lane = tid & 31;
    const int w = tid >> 5;
    const int wm0 = (w & 3) * 32;
    const int wn0 = (w >> 2) * 32;
    const int n0 = blockIdx.x * 128;
    const int m0 = blockIdx.y * 128;

    if (tid < 128) {
        int gc = n0 + tid;
        int wr = ((gc & 3) << 8) | (gc >> 2);
        bias_s[tid] = bih[wr] + bhh[wr];
    }

    float acc[2][4][4];
#pragma unroll
    for (int i = 0; i < 2; i++)
#pragma unroll
        for (int j = 0; j < 4; j++)
#pragma unroll
            for (int q = 0; q < 4; q++) acc[i][j][q] = 0.f;

    const int a_row = (lane & 15);
    const int a_kof = (lane >> 4) << 3;
    const int b_row = (lane & 7) + ((lane >> 4) << 3);
    const int b_kof = ((lane >> 3) & 1) << 3;

#pragma unroll
    for (int ch = 0; ch < 2; ch++) {
        const int kc0 = ch << 7;
        // ---- copy pre-split packed tiles into smem (8 positions/thread) ----
#pragma unroll
        for (int q = 0; q < 8; q++) {
            int p = tid + (q << 9);
            int r = p >> 5;
            int k = (p & 31) << 2;
            uint32_t so = (uint32_t)(r * RS + k) * 2;
            uint4 pa = *(const uint4*)&g_seqp[(size_t)(m0 + r) * HH + kc0 + k];
            *(uint64_t*)(sp + OFF_AHI + so) = up_hi(pa);
            *(uint64_t*)(sp + OFF_ALO + so) = up_lo(pa);
            uint4 pb = *(const uint4*)&wsp[(size_t)(n0 + r) * HH + kc0 + k];
            *(uint64_t*)(sp + OFF_BHI + so) = up_hi(pb);
            *(uint64_t*)(sp + OFF_BLO + so) = up_lo(pb);
        }
        __syncthreads();

#pragma unroll
        for (int ks = 0; ks < 8; ks++) {
            const int kb = ks << 4;
            uint32_t ah[2][4], al[2][4];
#pragma unroll
            for (int mt = 0; mt < 2; mt++) {
                uint32_t off = (uint32_t)((wm0 + mt * 16 + a_row) * RS + kb + a_kof) * 2;
                ldm4(ah[mt], sb + OFF_AHI + off);
                ldm4(al[mt], sb + OFF_ALO + off);
            }
#pragma unroll
            for (int np = 0; np < 2; np++) {
                uint32_t off = (uint32_t)((wn0 + np * 16 + b_row) * RS + kb + b_kof) * 2;
                uint32_t bh[4], bl[4];
                ldm4(bh, sb + OFF_BHI + off);
                ldm4(bl, sb + OFF_BLO + off);
#pragma unroll
                for (int mt = 0; mt < 2; mt++) {
                    mma_bf16(acc[mt][np * 2], ah[mt], bh[0], bh[1]);
                    mma_bf16(acc[mt][np * 2], ah[mt], bl[0], bl[1]);
                    mma_bf16(acc[mt][np * 2], al[mt], bh[0], bh[1]);
                    mma_bf16(acc[mt][np * 2 + 1], ah[mt], bh[2], bh[3]);
                    mma_bf16(acc[mt][np * 2 + 1], ah[mt], bl[2], bl[3]);
                    mma_bf16(acc[mt][np * 2 + 1], al[mt], bh[2], bh[3]);
                }
            }
        }
        __syncthreads();
    }

    float* stg = (float*)sp;
    const int g = lane >> 2, tg = lane & 3;
#pragma unroll
    for (int mt = 0; mt < 2; mt++)
#pragma unroll
        for (int nt = 0; nt < 4; nt++) {
            int row = wm0 + mt * 16 + g;
            int col = wn0 + nt * 8 + tg * 2;
            *(float2*)&stg[row * 132 + col] = make_float2(acc[mt][nt][0], acc[mt][nt][1]);
            *(float2*)&stg[(row + 8) * 132 + col] = make_float2(acc[mt][nt][2], acc[mt][nt][3]);
        }
    __syncthreads();

#pragma unroll
    for (int q = 0; q < 8; q++) {
        int p = tid + (q << 9);
        int r = p >> 5;
        int c = (p & 31) << 2;
        float4 o = *(const float4*)&stg[r * 132 + c];
        o.x += bias_s[c + 0];
        o.y += bias_s[c + 1];
        o.z += bias_s[c + 2];
        o.w += bias_s[c + 3];
        *(float4*)&g_xg[(size_t)(m0 + r) * G4 + n0 + c] = o;
    }
}

// ============ persistent LSTM layer: R13 shape (256 thr, 8 warps) + packed h ========
#define LRS 264
#define L_WHI 0
#define L_WLO (128 * LRS * 2)                // 67584
#define L_HHI (2 * 128 * LRS * 2)            // 135168
#define L_HLO (L_HHI + 32 * LRS * 2)         // 152064
#define L_STG (L_HLO + 32 * LRS * 2)         // 168960
#define LSTM_SMEM (L_STG + 32 * 132 * 4)     // 185856

template <bool WRITE_Y>
__global__ void __launch_bounds__(256, 1) lstm_layer(const float* __restrict__ whh,
                                                     float* __restrict__ out_h,
                                                     float* __restrict__ out_c) {
    extern __shared__ char sp[];
    const uint32_t sb = smem_u32(sp);
    float* stg = (float*)(sp + L_STG);

    const int tid = threadIdx.x;
    const int lane = tid & 31;
    const int w = tid >> 5;
    const int jb0 = (blockIdx.x & 7) << 5;
    const int grp = blockIdx.x >> 3;
    const int bb0 = grp << 5;

    // ---- stage weights bf16 hi/lo once (from fp32; one-time cost) ----
    {
        int c = tid & 127;
        int kh = (tid >> 7) << 7;
        int gate = c & 3, unit = c >> 2;
        const float* wrow = whh + (size_t)(gate * HH + jb0 + unit) * HH + kh;
#pragma unroll
        for (int q = 0; q < 32; q++) {
            float4 v = *(const float4*)(wrow + q * 4);
            uint32_t so = (uint32_t)(c * LRS + kh + q * 4) * 2;
            split_store(sp + L_WHI + so, sp + L_WLO + so, v);
        }
    }
    __syncthreads();

    const int a_row = lane & 15;
    const int a_kof = (lane >> 4) << 3;
    const int b_row = (lane & 7) + ((lane >> 4) << 3);
    const int b_kof = ((lane >> 3) & 1) << 3;
    const int wn0 = w << 4;              // this warp's 16 gate cols

    const int a4 = (tid >> 5) << 2;      // cell-update batch base
    const int jx = tid & 31;             // cell-update unit
    const int j = jb0 + jx;
    const int cb = tid >> 3;             // h-stage batch row 0..31
    const int ck = (tid & 7) << 2;       // h-stage k base

    float c_reg[4] = {0.f, 0.f, 0.f, 0.f};
    float hl[4] = {0.f, 0.f, 0.f, 0.f};

    for (int t = 0; t < SS; t++) {
        // prefetch this step's xg
        float4 xgv[4];
#pragma unroll
        for (int r = 0; r < 4; r++)
            xgv[r] = *(const float4*)&g_xg[((size_t)(bb0 + a4 + r) * SS + t) * G4 + (size_t)j * 4];

        if (t > 0) {
            // ---- unpack packed h_prev straight into ldmatrix tiles ----
            const uint32_t* hp = g_hp[t & 1] + (size_t)(bb0 + cb) * HH;
#pragma unroll
            for (int q = 0; q < 8; q++) {
                int k = ck + q * 32;
                uint4 pv = __ldcg((const uint4*)(hp + k));
                uint32_t so = (uint32_t)(cb * LRS + k) * 2;
                *(uint64_t*)(sp + L_HHI + so) = up_hi(pv);
                *(uint64_t*)(sp + L_HLO + so) = up_lo(pv);
            }
            __syncthreads();

            // ---- warp MMA: D[32 x 16cols] over K=256, 3-term bf16 split ----
            float acc[2][2][4];
#pragma unroll
            for (int mt = 0; mt < 2; mt++)
#pragma unroll
                for (int nt = 0; nt < 2; nt++)
#pragma unroll
                    for (int q = 0; q < 4; q++) acc[mt][nt][q] = 0.f;

#pragma unroll
            for (int ks = 0; ks < 16; ks++) {
                const int kb = ks << 4;
                uint32_t ah[2][4], al[2][4], bh[4], bl[4];
#pragma unroll
                for (int mt = 0; mt < 2; mt++) {
                    uint32_t off = (uint32_t)((mt * 16 + a_row) * LRS + kb + a_kof) * 2;
                    ldm4(ah[mt], sb + L_HHI + off);
                    ldm4(al[mt], sb + L_HLO + off);
                }
                {
                    uint32_t off = (uint32_t)((wn0 + b_row) * LRS + kb + b_kof) * 2;
                    ldm4(bh, sb + L_WHI + off);
                    ldm4(bl, sb + L_WLO + off);
                }
#pragma unroll
                for (int mt = 0; mt < 2; mt++) {
                    mma_bf16(acc[mt][0], ah[mt], bh[0], bh[1]);
                    mma_bf16(acc[mt][0], ah[mt], bl[0], bl[1]);
                    mma_bf16(acc[mt][0], al[mt], bh[0], bh[1]);
                    mma_bf16(acc[mt][1], ah[mt], bh[2], bh[3]);
                    mma_bf16(acc[mt][1], ah[mt], bl[2], bl[3]);
                    mma_bf16(acc[mt][1], al[mt], bh[2], bh[3]);
                }
            }

            // ---- stage acc -> stg[32][132] ----
            int gg = lane >> 2, tg = lane & 3;
#pragma unroll
            for (int mt = 0; mt < 2; mt++)
#pragma unroll
                for (int nt = 0; nt < 2; nt++) {
                    int row = mt * 16 + gg;
                    int col = wn0 + nt * 8 + tg * 2;
                    *(float2*)&stg[row * 132 + col] = make_float2(acc[mt][nt][0], acc[mt][nt][1]);
                    *(float2*)&stg[(row + 8) * 132 + col] = make_float2(acc[mt][nt][2], acc[mt][nt][3]);
                }
            __syncthreads();
        }

        // ---- cell update; h written packed (identical split values) ----
        uint32_t* hnext = g_hp[(t & 1) ^ 1];
#pragma unroll
        for (int r = 0; r < 4; r++) {
            int bl_ = a4 + r;
            float4 gv = (t > 0) ? *(const float4*)&stg[bl_ * 132 + (jx << 2)]
                                : make_float4(0.f, 0.f, 0.f, 0.f);
            float iv = sigm(gv.x + xgv[r].x);
            float fv = sigm(gv.y + xgv[r].y);
            float gt = tanhf(gv.z + xgv[r].z);
            float ov = sigm(gv.w + xgv[r].w);
            c_reg[r] = fmaf(fv, c_reg[r], iv * gt);
            float hn = ov * tanhf(c_reg[r]);
            hl[r] = hn;
            int b = bb0 + bl_;
            uint32_t ps = packsplit(hn);
            hnext[(size_t)b * HH + j] = ps;
            if (WRITE_Y) g_seqp[((size_t)b * SS + t) * HH + j] = ps;
        }

        group_sync(grp);
    }

    // epilogue: final h/c from registers (head reads out_h directly)
#pragma unroll
    for (int r = 0; r < 4; r++) {
        size_t idx = (size_t)(bb0 + a4 + r) * HH + j;
        out_h[idx] = hl[r];
        out_c[idx] = c_reg[r];
    }
}

// -------- head: layernorm(h1) -> relu(w1) -> w2 -> mask --------
__global__ void head_kernel(const float* __restrict__ h1,
                            const float* __restrict__ mask,
                            const float* __restrict__ ln_g, const float* __restrict__ ln_b,
                            const float* __restrict__ w1, const float* __restrict__ b1,
                            const float* __restrict__ w2, const float* __restrict__ b2,
                            float* __restrict__ out_logits) {
    int b = blockIdx.x;
    int tid = threadIdx.x;
    __shared__ float sh[HH];
    __shared__ float r1[8], r2[8];
    __shared__ float stats[2];
    __shared__ float hdn[32];

    float v = h1[(size_t)b * HH + tid];
    float s1 = v, s2 = v * v;
#pragma unroll
    for (int off = 16; off > 0; off >>= 1) {
        s1 += __shfl_down_sync(0xffffffffu, s1, off);
        s2 += __shfl_down_sync(0xffffffffu, s2, off);
    }
    if ((tid & 31) == 0) { r1[tid >> 5] = s1; r2[tid >> 5] = s2; }
    __syncthreads();
    if (tid == 0) {
        float t1 = 0.f, t2 = 0.f;
        for (int i = 0; i < 8; i++) { t1 += r1[i]; t2 += r2[i]; }
        float mu = t1 * (1.f / HH);
        float var = t2 * (1.f / HH) - mu * mu;
        stats[0] = mu;
        stats[1] = rsqrtf(var + 1e-5f);
    }
    __syncthreads();
    sh[tid] = (v - stats[0]) * stats[1] * ln_g[tid] + ln_b[tid];
    __syncthreads();

    int u = tid >> 3, p = tid & 7;
    float part = 0.f;
#pragma unroll
    for (int k = p; k < HH; k += 8) part = fmaf(sh[k], w1[u * HH + k], part);
    part += __shfl_down_sync(0xffffffffu, part, 4);
    part += __shfl_down_sync(0xffffffffu, part, 2);
    part += __shfl_down_sync(0xffffffffu, part, 1);
    if (p == 0) hdn[u] = fmaxf(part + b1[u], 0.f);
    __syncthreads();

    if (tid < AA) {
        float acc = b2[tid];
#pragma unroll
        for (int k = 0; k < 32; k++) acc = fmaf(hdn[k], w2[tid * 32 + k], acc);
        acc += (1.f - mask[(size_t)b * AA + tid]) * -1e9f;
        out_logits[(size_t)b * AA + tid] = acc;
    }
}

extern "C" void kernel_launch(void* const* d_in, const int* in_sizes, int n_in,
                              void* d_out, int out_size) {
    (void)in_sizes; (void)n_in; (void)out_size;
    const float* x     = (const float*)d_in[0];
    const float* mask  = (const float*)d_in[1];
    const float* W_emb = (const float*)d_in[2];
    const float* b_emb = (const float*)d_in[3];
    const float* w_ih0 = (const float*)d_in[4];
    const float* w_hh0 = (const float*)d_in[5];
    const float* b_ih0 = (const float*)d_in[6];
    const float* b_hh0 = (const float*)d_in[7];
    const float* w_ih1 = (const float*)d_in[8];
    const float* w_hh1 = (const float*)d_in[9];
    const float* b_ih1 = (const float*)d_in[10];
    const float* b_hh1 = (const float*)d_in[11];
    const float* ln_g  = (const float*)d_in[12];
    const float* ln_b  = (const float*)d_in[13];
    const float* w1    = (const float*)d_in[14];
    const float* b1    = (const float*)d_in[15];
    const float* w2    = (const float*)d_in[16];
    const float* b2    = (const float*)d_in[17];

    float* out        = (float*)d_out;
    float* out_logits = out;
    float* out_h0     = out + BB * AA;
    float* out_h1     = out_h0 + BB * HH;
    float* out_c0     = out_h1 + BB * HH;
    float* out_c1     = out_c0 + BB * HH;

    uint32_t* wsp0;
    uint32_t* wsp1;
    cudaGetSymbolAddress((void**)&wsp0, g_wsp0);
    cudaGetSymbolAddress((void**)&wsp1, g_wsp1);

    cudaFuncSetAttribute(lstm_layer<true>,
                         cudaFuncAttributeMaxDynamicSharedMemorySize, LSTM_SMEM);
    cudaFuncSetAttribute(lstm_layer<false>,
                         cudaFuncAttributeMaxDynamicSharedMemorySize, LSTM_SMEM);
    cudaFuncSetAttribute(xg_mma,
                         cudaFuncAttributeMaxDynamicSharedMemorySize, XG_SMEM);

    dim3 xg_grid(G4 / 128, (BB * SS) / 128);   // (8, 1024)

    // pre-split both input weight matrices + embedding (independent; front-loaded)
    wsplit_kernel<<<G4, 256>>>(w_ih0, wsp0);
    wsplit_kernel<<<G4, 256>>>(w_ih1, wsp1);
    emb_kernel<<<(BB * SS) / 8, 256>>>(x, W_emb, b_emb);

    // layer 0
    xg_mma<<<xg_grid, 512, XG_SMEM>>>(wsp0, b_ih0, b_hh0);
    lstm_layer<true><<<NCTA, 256, LSTM_SMEM>>>(w_hh0, out_h0, out_c0);

    // layer 1 (packed y0 in g_seqp)
    xg_mma<<<xg_grid, 512, XG_SMEM>>>(wsp1, b_ih1, b_hh1);
    lstm_layer<false><<<NCTA, 256, LSTM_SMEM>>>(w_hh1, out_h1, out_c1);

    // head: last == final h1 (written to out_h1 by lstm epilogue)
    head_kernel<<<BB, 256>>>(out_h1, mask, ln_g, ln_b, w1, b1, w2, b2, out_logits);
}